// round 1
// baseline (speedup 1.0000x reference)
#include <cuda_runtime.h>
#include <math.h>
#include <stdint.h>

// ---------------- problem constants ----------------
#define BATCH 8
#define CHN 3
#define IMG 224
#define PATCH 16
#define GRID 14
#define NPATCH 196        // GRID*GRID
#define SEQ 197           // NPATCH + 1
#define DIM 768
#define NHEAD 12
#define HDIM 64
#define NLAYER 12
#define TOPK 32
#define MLPDIM 3072
#define ATT_SCALE 0.125f  // 64^-0.5

#define NROWS (BATCH*SEQ)           // 1576
#define NROWS_P (BATCH*NPATCH)      // 1568

// ---------------- scratch (device globals; no allocation allowed) ----------------
__device__ float g_h  [BATCH*SEQ*DIM];
__device__ float g_xn [BATCH*SEQ*DIM];
__device__ float g_qkv[BATCH*SEQ*3*DIM];
__device__ float g_att[BATCH*SEQ*DIM];
__device__ float g_mlp[BATCH*SEQ*MLPDIM];

// ---------------- GEMM: C[n,m] = sum_k A[n,k]*W[m,k] + bias[m] (+epilogue) ----------
// EPI: 0 = bias only, 1 = bias + exact GELU, 2 = bias + residual add
// Tile: BM=128 rows, BN=64 cols, BK=16. 256 threads, 8x4 per-thread tile.
template<int EPI>
__global__ void __launch_bounds__(256)
gemm_bias(const float* __restrict__ A, const float* __restrict__ W,
          const float* __restrict__ bias, const float* __restrict__ res,
          float* __restrict__ C, int N, int K, int M)
{
    __shared__ float As[16][128];
    __shared__ float Ws[16][64];

    const int tid  = threadIdx.x;
    const int row0 = blockIdx.y * 128;
    const int col0 = blockIdx.x * 64;

    const int lr = tid >> 2;          // 0..63
    const int lk = (tid & 3) * 4;     // 0,4,8,12
    const int tx = tid & 15;          // col group
    const int ty = tid >> 4;          // row group

    float acc[8][4];
#pragma unroll
    for (int i = 0; i < 8; i++)
#pragma unroll
        for (int j = 0; j < 4; j++) acc[i][j] = 0.f;

    for (int k0 = 0; k0 < K; k0 += 16) {
        // load A tile: 128x16 (two rows per thread), guard ragged N
#pragma unroll
        for (int t = 0; t < 2; t++) {
            int r  = lr + t * 64;
            int gr = row0 + r;
            float4 v = make_float4(0.f, 0.f, 0.f, 0.f);
            if (gr < N)
                v = *reinterpret_cast<const float4*>(A + (size_t)gr * K + k0 + lk);
            As[lk + 0][r] = v.x; As[lk + 1][r] = v.y;
            As[lk + 2][r] = v.z; As[lk + 3][r] = v.w;
        }
        // load W tile: 64x16 (M always multiple of 64 here)
        {
            int gc = col0 + lr;
            float4 v = *reinterpret_cast<const float4*>(W + (size_t)gc * K + k0 + lk);
            Ws[lk + 0][lr] = v.x; Ws[lk + 1][lr] = v.y;
            Ws[lk + 2][lr] = v.z; Ws[lk + 3][lr] = v.w;
        }
        __syncthreads();

#pragma unroll
        for (int kk = 0; kk < 16; kk++) {
            float4 b4 = *reinterpret_cast<const float4*>(&Ws[kk][tx * 4]);
            float4 a0 = *reinterpret_cast<const float4*>(&As[kk][ty * 8]);
            float4 a1 = *reinterpret_cast<const float4*>(&As[kk][ty * 8 + 4]);
            float a[8] = {a0.x, a0.y, a0.z, a0.w, a1.x, a1.y, a1.z, a1.w};
            float b[4] = {b4.x, b4.y, b4.z, b4.w};
#pragma unroll
            for (int i = 0; i < 8; i++)
#pragma unroll
                for (int j = 0; j < 4; j++)
                    acc[i][j] = fmaf(a[i], b[j], acc[i][j]);
        }
        __syncthreads();
    }

#pragma unroll
    for (int i = 0; i < 8; i++) {
        int r = row0 + ty * 8 + i;
        if (r >= N) continue;
#pragma unroll
        for (int j = 0; j < 4; j++) {
            int c = col0 + tx * 4 + j;
            float v = acc[i][j] + bias[c];
            if (EPI == 1) {
                v = 0.5f * v * (1.0f + erff(v * 0.7071067811865475f));
            } else if (EPI == 2) {
                v += res[(size_t)r * M + c];
            }
            C[(size_t)r * M + c] = v;
        }
    }
}

// ---------------- LayerNorm: one block per row ----------------
__global__ void __launch_bounds__(256)
ln_kernel(const float* __restrict__ x, const float* __restrict__ s,
          const float* __restrict__ b, float* __restrict__ y)
{
    const int row = blockIdx.x;
    const int tid = threadIdx.x;
    const float* xr = x + (size_t)row * DIM;

    float v0 = xr[tid];
    float v1 = xr[tid + 256];
    float v2 = xr[tid + 512];

    __shared__ float ssum[256], ssq[256];
    ssum[tid] = v0 + v1 + v2;
    ssq[tid]  = v0 * v0 + v1 * v1 + v2 * v2;
    __syncthreads();
    for (int st = 128; st > 0; st >>= 1) {
        if (tid < st) { ssum[tid] += ssum[tid + st]; ssq[tid] += ssq[tid + st]; }
        __syncthreads();
    }
    const float mean = ssum[0] * (1.0f / DIM);
    const float var  = ssq[0] * (1.0f / DIM) - mean * mean;
    const float inv  = rsqrtf(var + 1e-5f);

    float* yr = y + (size_t)row * DIM;
    yr[tid]       = (v0 - mean) * inv * s[tid]       + b[tid];
    yr[tid + 256] = (v1 - mean) * inv * s[tid + 256] + b[tid + 256];
    yr[tid + 512] = (v2 - mean) * inv * s[tid + 512] + b[tid + 512];
}

// ---------------- Attention: one warp per (b, h, query) ----------------
// qkv row (b*SEQ+s), col layout: t*768 + h*64 + hd (t = 0:Q, 1:K, 2:V)
__global__ void __launch_bounds__(128)
attn_kernel(const float* __restrict__ qkv, const int* __restrict__ routes,
            float* __restrict__ out)
{
    __shared__ float sc[4][200];
    __shared__ int   sidx[4][200];
    __shared__ float qs[4][64];

    const int bh   = blockIdx.x;
    const int b    = bh / NHEAD;
    const int h    = bh % NHEAD;
    const int warp = threadIdx.x >> 5;
    const int lane = threadIdx.x & 31;
    const int s    = blockIdx.y * 4 + warp;
    if (s >= SEQ) return;

    const float* base = qkv + (size_t)b * SEQ * (3 * DIM);
    const float* qp = base + (size_t)s * (3 * DIM) + h * HDIM;
    qs[warp][lane]      = qp[lane];
    qs[warp][lane + 32] = qp[lane + 32];
    __syncwarp();

    const int nk = (s == 0) ? SEQ : TOPK;

    for (int j = lane; j < nk; j += 32) {
        int kidx = (s == 0) ? j : (routes[(s - 1) * TOPK + j] + 1);
        const float* kp = base + (size_t)kidx * (3 * DIM) + DIM + h * HDIM;
        float acc = 0.f;
#pragma unroll
        for (int d = 0; d < HDIM; d++) acc = fmaf(qs[warp][d], kp[d], acc);
        sc[warp][j]   = acc * ATT_SCALE;
        sidx[warp][j] = kidx;
    }
    __syncwarp();

    float m = -1e30f;
    for (int j = lane; j < nk; j += 32) m = fmaxf(m, sc[warp][j]);
#pragma unroll
    for (int o = 16; o; o >>= 1) m = fmaxf(m, __shfl_xor_sync(0xffffffffu, m, o));

    float sum = 0.f;
    for (int j = lane; j < nk; j += 32) {
        float e = expf(sc[warp][j] - m);
        sc[warp][j] = e;
        sum += e;
    }
#pragma unroll
    for (int o = 16; o; o >>= 1) sum += __shfl_xor_sync(0xffffffffu, sum, o);
    __syncwarp();
    const float inv = 1.f / sum;

    float o0 = 0.f, o1 = 0.f;
    for (int j = 0; j < nk; j++) {
        float p = sc[warp][j];
        const float* vp = base + (size_t)sidx[warp][j] * (3 * DIM) + 2 * DIM + h * HDIM;
        o0 = fmaf(p, vp[2 * lane],     o0);
        o1 = fmaf(p, vp[2 * lane + 1], o1);
    }
    size_t ob = ((size_t)(b * SEQ + s)) * DIM + h * HDIM;
    out[ob + 2 * lane]     = o0 * inv;
    out[ob + 2 * lane + 1] = o1 * inv;
}

// ---------------- Patchify: x (B,C,224,224) -> xp (B*196, 768) ----------------
__global__ void patchify_kernel(const float* __restrict__ x, float* __restrict__ xp)
{
    int idx = blockIdx.x * blockDim.x + threadIdx.x;
    const int total = NROWS_P * DIM;
    if (idx >= total) return;
    int e  = idx % DIM;
    int bp = idx / DIM;
    int p  = bp % NPATCH;
    int b  = bp / NPATCH;
    int c  = e / (PATCH * PATCH);
    int r  = e % (PATCH * PATCH);
    int py = r / PATCH, px = r % PATCH;
    int gy = p / GRID,  gx = p % GRID;
    xp[idx] = x[(((size_t)b * CHN + c) * IMG + gy * PATCH + py) * IMG + gx * PATCH + px];
}

// ---------------- Assemble h = concat(cls, tok) + pos ----------------
__global__ void assemble_kernel(const float* __restrict__ tok, const float* __restrict__ cls,
                                const float* __restrict__ pos, float* __restrict__ hout)
{
    int idx = blockIdx.x * blockDim.x + threadIdx.x;
    const int total = BATCH * SEQ * DIM;
    if (idx >= total) return;
    int d  = idx % DIM;
    int bs = idx / DIM;
    int s  = bs % SEQ;
    int b  = bs / SEQ;
    float v = (s == 0) ? cls[d] : tok[((size_t)b * NPATCH + (s - 1)) * DIM + d];
    hout[idx] = v + pos[(size_t)s * DIM + d];
}

// ---------------- host launcher ----------------
extern "C" void kernel_launch(void* const* d_in, const int* in_sizes, int n_in,
                              void* d_out, int out_size)
{
    const float* x        = (const float*)d_in[0];
    const float* patch_w  = (const float*)d_in[1];
    const float* patch_b  = (const float*)d_in[2];
    const float* cls_tok  = (const float*)d_in[3];
    const float* pos_emb  = (const float*)d_in[4];
    const float* qkv_w    = (const float*)d_in[5];
    const float* qkv_b    = (const float*)d_in[6];
    const float* proj_w   = (const float*)d_in[7];
    const float* proj_b   = (const float*)d_in[8];
    const float* ln1_s    = (const float*)d_in[9];
    const float* ln1_b    = (const float*)d_in[10];
    const float* ln2_s    = (const float*)d_in[11];
    const float* ln2_b    = (const float*)d_in[12];
    const float* fc1_w    = (const float*)d_in[13];
    const float* fc1_b    = (const float*)d_in[14];
    const float* fc2_w    = (const float*)d_in[15];
    const float* fc2_b    = (const float*)d_in[16];
    const int*   routes   = (const int*)d_in[17];

    float *hbuf, *xn, *qkv, *att, *mlp;
    cudaGetSymbolAddress((void**)&hbuf, g_h);
    cudaGetSymbolAddress((void**)&xn,   g_xn);
    cudaGetSymbolAddress((void**)&qkv,  g_qkv);
    cudaGetSymbolAddress((void**)&att,  g_att);
    cudaGetSymbolAddress((void**)&mlp,  g_mlp);

    const int rt128 = (NROWS + 127) / 128;     // 13
    const int rtp   = (NROWS_P + 127) / 128;   // 13

    // patch embed: xp -> g_mlp (scratch), tok -> g_att, assemble -> g_h
    {
        int tot = NROWS_P * DIM;
        patchify_kernel<<<(tot + 255) / 256, 256>>>(x, mlp);
        gemm_bias<0><<<dim3(DIM / 64, rtp), 256>>>(mlp, patch_w, patch_b, nullptr, att,
                                                   NROWS_P, DIM, DIM);
        int tot2 = BATCH * SEQ * DIM;
        assemble_kernel<<<(tot2 + 255) / 256, 256>>>(att, cls_tok, pos_emb, hbuf);
    }

    for (int l = 0; l < NLAYER; l++) {
        const float* qw  = qkv_w  + (size_t)l * 3 * DIM * DIM;
        const float* qb  = qkv_b  + (size_t)l * 3 * DIM;
        const float* pw  = proj_w + (size_t)l * DIM * DIM;
        const float* pb  = proj_b + (size_t)l * DIM;
        const float* f1w = fc1_w  + (size_t)l * MLPDIM * DIM;
        const float* f1b = fc1_b  + (size_t)l * MLPDIM;
        const float* f2w = fc2_w  + (size_t)l * DIM * MLPDIM;
        const float* f2b = fc2_b  + (size_t)l * DIM;

        // LN1
        ln_kernel<<<NROWS, 256>>>(hbuf, ln1_s + (size_t)l * DIM, ln1_b + (size_t)l * DIM, xn);
        // QKV: (1576,768) x (2304,768)^T
        gemm_bias<0><<<dim3(3 * DIM / 64, rt128), 256>>>(xn, qw, qb, nullptr, qkv,
                                                         NROWS, DIM, 3 * DIM);
        // attention
        attn_kernel<<<dim3(BATCH * NHEAD, (SEQ + 3) / 4), 128>>>(qkv, routes, att);
        // proj + residual into h
        gemm_bias<2><<<dim3(DIM / 64, rt128), 256>>>(att, pw, pb, hbuf, hbuf,
                                                     NROWS, DIM, DIM);
        // LN2
        ln_kernel<<<NROWS, 256>>>(hbuf, ln2_s + (size_t)l * DIM, ln2_b + (size_t)l * DIM, xn);
        // fc1 + gelu
        gemm_bias<1><<<dim3(MLPDIM / 64, rt128), 256>>>(xn, f1w, f1b, nullptr, mlp,
                                                        NROWS, DIM, MLPDIM);
        // fc2 + residual; last layer writes straight to d_out
        float* outp = (l == NLAYER - 1) ? (float*)d_out : hbuf;
        gemm_bias<2><<<dim3(DIM / 64, rt128), 256>>>(mlp, f2w, f2b, hbuf, outp,
                                                     NROWS, MLPDIM, DIM);
    }
}

// round 3
// speedup vs baseline: 2.0106x; 2.0106x over previous
#include <cuda_runtime.h>
#include <cuda_bf16.h>
#include <math.h>
#include <stdint.h>

// ---------------- problem constants ----------------
#define BATCH 8
#define CHN 3
#define IMG 224
#define PATCH 16
#define GRID 14
#define NPATCH 196
#define SEQ 197
#define DIM 768
#define NHEAD 12
#define HDIM 64
#define NLAYER 12
#define TOPK 32
#define MLPDIM 3072
#define ATT_SCALE 0.125f

#define NROWS (BATCH*SEQ)           // 1576
#define NROWS_P (BATCH*NPATCH)      // 1568

// weight-buffer element offsets (concatenated bf16 hi/lo arrays)
#define NW_PATCH (DIM*DIM)                        // 589824
#define NW_QKV   (NLAYER*3*DIM*DIM)               // 21233664
#define NW_PROJ  (NLAYER*DIM*DIM)                 // 7077888
#define NW_FC1   (NLAYER*MLPDIM*DIM)              // 28311552
#define NW_FC2   (NLAYER*DIM*MLPDIM)              // 28311552
#define OFF_PATCH 0
#define OFF_QKV   (OFF_PATCH + NW_PATCH)
#define OFF_PROJ  (OFF_QKV + NW_QKV)
#define OFF_FC1   (OFF_PROJ + NW_PROJ)
#define OFF_FC2   (OFF_FC1 + NW_FC1)
#define NW_TOTAL  (OFF_FC2 + NW_FC2)              // 85524480

// ---------------- scratch ----------------
__device__ float g_h  [BATCH*SEQ*DIM];
__device__ float g_xn [BATCH*SEQ*DIM];
__device__ float g_qkv[BATCH*SEQ*3*DIM];
__device__ float g_att[BATCH*SEQ*DIM];
__device__ float g_mlp[BATCH*SEQ*MLPDIM];
__device__ __nv_bfloat16 g_wh[NW_TOTAL];
__device__ __nv_bfloat16 g_wl[NW_TOTAL];

// ---------------- small helpers ----------------
__device__ __forceinline__ uint32_t smem_u32(const void* p) {
    uint32_t a;
    asm("{ .reg .u64 t; cvta.to.shared.u64 t, %1; cvt.u32.u64 %0, t; }" : "=r"(a) : "l"(p));
    return a;
}
__device__ __forceinline__ uint32_t pack_bf16(__nv_bfloat16 a, __nv_bfloat16 b) {
    return (uint32_t)__bfloat16_as_ushort(a) | ((uint32_t)__bfloat16_as_ushort(b) << 16);
}

__device__ __forceinline__ void ldmx4(uint32_t& r0, uint32_t& r1, uint32_t& r2, uint32_t& r3,
                                      uint32_t addr) {
    asm volatile("ldmatrix.sync.aligned.m8n8.x4.shared.b16 {%0,%1,%2,%3}, [%4];"
                 : "=r"(r0), "=r"(r1), "=r"(r2), "=r"(r3) : "r"(addr));
}
__device__ __forceinline__ void mma16816(float* d, const uint32_t* a, uint32_t b0, uint32_t b1) {
    asm volatile(
        "mma.sync.aligned.m16n8k16.row.col.f32.bf16.bf16.f32 "
        "{%0,%1,%2,%3},{%4,%5,%6,%7},{%8,%9},{%0,%1,%2,%3};"
        : "+f"(d[0]), "+f"(d[1]), "+f"(d[2]), "+f"(d[3])
        : "r"(a[0]), "r"(a[1]), "r"(a[2]), "r"(a[3]), "r"(b0), "r"(b1));
}

// split fp32 -> bf16 hi + bf16 lo
__device__ __forceinline__ void split8(const float* f, uint4& H, uint4& L) {
    __nv_bfloat16 h[8];
    __nv_bfloat16 l[8];
#pragma unroll
    for (int i = 0; i < 8; i++) {
        h[i] = __float2bfloat16(f[i]);
        l[i] = __float2bfloat16(f[i] - __bfloat162float(h[i]));
    }
    H.x = pack_bf16(h[0], h[1]); H.y = pack_bf16(h[2], h[3]);
    H.z = pack_bf16(h[4], h[5]); H.w = pack_bf16(h[6], h[7]);
    L.x = pack_bf16(l[0], l[1]); L.y = pack_bf16(l[2], l[3]);
    L.z = pack_bf16(l[4], l[5]); L.w = pack_bf16(l[6], l[7]);
}

// ---------------- weight pre-conversion (runs every launch; deterministic) ----------------
__global__ void __launch_bounds__(256)
cvt_weights(const float* __restrict__ src, __nv_bfloat16* __restrict__ hi,
            __nv_bfloat16* __restrict__ lo, int n4)
{
    int i = blockIdx.x * blockDim.x + threadIdx.x;
    if (i >= n4) return;
    float4 f = reinterpret_cast<const float4*>(src)[i];
    __nv_bfloat16 h0 = __float2bfloat16(f.x), h1 = __float2bfloat16(f.y);
    __nv_bfloat16 h2 = __float2bfloat16(f.z), h3 = __float2bfloat16(f.w);
    uint2 H, L;
    H.x = pack_bf16(h0, h1); H.y = pack_bf16(h2, h3);
    L.x = pack_bf16(__float2bfloat16(f.x - __bfloat162float(h0)),
                    __float2bfloat16(f.y - __bfloat162float(h1)));
    L.y = pack_bf16(__float2bfloat16(f.z - __bfloat162float(h2)),
                    __float2bfloat16(f.w - __bfloat162float(h3)));
    reinterpret_cast<uint2*>(hi)[i] = H;
    reinterpret_cast<uint2*>(lo)[i] = L;
}

// ---------------- HMMA GEMM ----------------
// C[n,m] = sum_k A[n,k] * W[m,k] + bias[m] (+epilogue)
// A fp32 (converted in-kernel to bf16 hi/lo); W pre-converted bf16 hi/lo.
// Block 128x64, BK=32, 256 threads = 8 warps (4m x 2n), warp tile 32x32.
// bf16x3: AhWh + AhWl + AlWh, fp32 accum.
// EPI: 0 bias, 1 bias+GELU(exact), 2 bias+residual
template<int EPI>
__global__ void __launch_bounds__(256)
hgemm(const float* __restrict__ A,
      const __nv_bfloat16* __restrict__ Wh, const __nv_bfloat16* __restrict__ Wl,
      const float* __restrict__ bias, const float* __restrict__ res,
      float* __restrict__ C, int Nrows, int K, int M)
{
    constexpr int BM = 128, BN = 64, BK = 32;
    constexpr int ASTB = 80;                  // bytes per smem row (32*2 + 16 pad)
    constexpr int ABYTES = BM * ASTB;         // 10240
    constexpr int BBYTES = BN * ASTB;         // 5120
    constexpr int STAGE = 2 * ABYTES + 2 * BBYTES;   // 30720
    // stage offsets
    constexpr int O_AH = 0, O_AL = ABYTES, O_BH = 2 * ABYTES, O_BL = 2 * ABYTES + BBYTES;

    extern __shared__ char sm[];
    const uint32_t sbase = smem_u32(sm);

    const int tid  = threadIdx.x;
    const int lane = tid & 31;
    const int wid  = tid >> 5;
    const int wm   = wid & 3;     // 0..3 -> m offset 32*wm
    const int wn   = wid >> 2;    // 0..1 -> n offset 32*wn
    const int row0 = blockIdx.y * BM;
    const int col0 = blockIdx.x * BN;

    // ---- staging assignments ----
    // A: 128 rows x 4 chunks(8 fp32) = 512 units; 2 per thread
    const int ar0 = tid >> 2;               // unit 0 row
    const int ar1 = (tid + 256) >> 2;       // unit 1 row
    const int aq  = tid & 3;                // chunk
    const bool av0 = (row0 + ar0) < Nrows;
    const bool av1 = (row0 + ar1) < Nrows;
    const float* aP0 = A + (size_t)(row0 + ar0) * K + aq * 8;
    const float* aP1 = A + (size_t)(row0 + ar1) * K + aq * 8;
    // B: 64 rows x 4 chunks(8 bf16 = 16B) = 256 units; 1 per thread
    const int br = tid >> 2;
    const int bq = tid & 3;
    const __nv_bfloat16* bhP = Wh + (size_t)(col0 + br) * K + bq * 8;
    const __nv_bfloat16* blP = Wl + (size_t)(col0 + br) * K + bq * 8;

    const uint32_t stA0 = (uint32_t)(ar0 * ASTB + aq * 16);
    const uint32_t stA1 = (uint32_t)(ar1 * ASTB + aq * 16);
    const uint32_t stB  = (uint32_t)(br * ASTB + bq * 16);

    // ---- ldmatrix addresses (within a stage) ----
    // A frags: rows wm*32 + mi*16 + (lane&15), koff (lane>>4)*16 (+k16*32)
    uint32_t aoff[2], boff[2];
#pragma unroll
    for (int mi = 0; mi < 2; mi++)
        aoff[mi] = (uint32_t)((wm * 32 + mi * 16 + (lane & 15)) * ASTB + (lane >> 4) * 16);
    // B frags: rows wn*32 + nj2*16 + (lane&7) + ((lane>>4)<<3), koff ((lane>>3)&1)*16
#pragma unroll
    for (int nj2 = 0; nj2 < 2; nj2++)
        boff[nj2] = (uint32_t)((wn * 32 + nj2 * 16 + (lane & 7) + ((lane >> 4) << 3)) * ASTB
                               + ((lane >> 3) & 1) * 16);

    float acc[2][4][4];
#pragma unroll
    for (int mi = 0; mi < 2; mi++)
#pragma unroll
        for (int nj = 0; nj < 4; nj++)
#pragma unroll
            for (int v = 0; v < 4; v++) acc[mi][nj][v] = 0.f;

    const int KT = K / BK;

    // prefetch registers
    float af[2][8];
    uint4 bhr, blr;

    // load stage 0
    {
#pragma unroll
        for (int v = 0; v < 8; v++) { af[0][v] = 0.f; af[1][v] = 0.f; }
        if (av0) {
            *reinterpret_cast<float4*>(&af[0][0]) = *reinterpret_cast<const float4*>(aP0);
            *reinterpret_cast<float4*>(&af[0][4]) = *reinterpret_cast<const float4*>(aP0 + 4);
        }
        if (av1) {
            *reinterpret_cast<float4*>(&af[1][0]) = *reinterpret_cast<const float4*>(aP1);
            *reinterpret_cast<float4*>(&af[1][4]) = *reinterpret_cast<const float4*>(aP1 + 4);
        }
        bhr = *reinterpret_cast<const uint4*>(bhP);
        blr = *reinterpret_cast<const uint4*>(blP);
    }

    for (int kt = 0; kt < KT; kt++) {
        const int s = kt & 1;
        char* sb = sm + s * STAGE;

        // store prefetched tile
        {
            uint4 H, L;
            split8(af[0], H, L);
            *reinterpret_cast<uint4*>(sb + O_AH + stA0) = H;
            *reinterpret_cast<uint4*>(sb + O_AL + stA0) = L;
            split8(af[1], H, L);
            *reinterpret_cast<uint4*>(sb + O_AH + stA1) = H;
            *reinterpret_cast<uint4*>(sb + O_AL + stA1) = L;
            *reinterpret_cast<uint4*>(sb + O_BH + stB) = bhr;
            *reinterpret_cast<uint4*>(sb + O_BL + stB) = blr;
        }
        __syncthreads();

        // issue next-stage global loads
        if (kt + 1 < KT) {
            const int ko = (kt + 1) * BK;
#pragma unroll
            for (int v = 0; v < 8; v++) { af[0][v] = 0.f; af[1][v] = 0.f; }
            if (av0) {
                *reinterpret_cast<float4*>(&af[0][0]) = *reinterpret_cast<const float4*>(aP0 + ko);
                *reinterpret_cast<float4*>(&af[0][4]) = *reinterpret_cast<const float4*>(aP0 + ko + 4);
            }
            if (av1) {
                *reinterpret_cast<float4*>(&af[1][0]) = *reinterpret_cast<const float4*>(aP1 + ko);
                *reinterpret_cast<float4*>(&af[1][4]) = *reinterpret_cast<const float4*>(aP1 + ko + 4);
            }
            bhr = *reinterpret_cast<const uint4*>(bhP + ko);
            blr = *reinterpret_cast<const uint4*>(blP + ko);
        }

        // compute this stage
        const uint32_t sb32 = sbase + (uint32_t)(s * STAGE);
#pragma unroll
        for (int k16 = 0; k16 < 2; k16++) {
            const uint32_t kb = (uint32_t)(k16 * 32);
            uint32_t ah[2][4], al[2][4], bh[2][4], bl[2][4];
#pragma unroll
            for (int mi = 0; mi < 2; mi++) {
                ldmx4(ah[mi][0], ah[mi][1], ah[mi][2], ah[mi][3], sb32 + O_AH + aoff[mi] + kb);
                ldmx4(al[mi][0], al[mi][1], al[mi][2], al[mi][3], sb32 + O_AL + aoff[mi] + kb);
            }
#pragma unroll
            for (int nj2 = 0; nj2 < 2; nj2++) {
                ldmx4(bh[nj2][0], bh[nj2][1], bh[nj2][2], bh[nj2][3], sb32 + O_BH + boff[nj2] + kb);
                ldmx4(bl[nj2][0], bl[nj2][1], bl[nj2][2], bl[nj2][3], sb32 + O_BL + boff[nj2] + kb);
            }
#pragma unroll
            for (int mi = 0; mi < 2; mi++)
#pragma unroll
                for (int nj = 0; nj < 4; nj++) {
                    const uint32_t b0h = bh[nj >> 1][(nj & 1) * 2];
                    const uint32_t b1h = bh[nj >> 1][(nj & 1) * 2 + 1];
                    const uint32_t b0l = bl[nj >> 1][(nj & 1) * 2];
                    const uint32_t b1l = bl[nj >> 1][(nj & 1) * 2 + 1];
                    mma16816(acc[mi][nj], ah[mi], b0h, b1h);
                    mma16816(acc[mi][nj], ah[mi], b0l, b1l);
                    mma16816(acc[mi][nj], al[mi], b0h, b1h);
                }
        }
    }

    // ---- epilogue ----
    const int g  = lane >> 2;
    const int tg = lane & 3;
#pragma unroll
    for (int mi = 0; mi < 2; mi++) {
#pragma unroll
        for (int half = 0; half < 2; half++) {
            const int r = row0 + wm * 32 + mi * 16 + g + half * 8;
            if (r >= Nrows) continue;
#pragma unroll
            for (int nj = 0; nj < 4; nj++) {
                const int c = col0 + wn * 32 + nj * 8 + tg * 2;
                float v0 = acc[mi][nj][half * 2 + 0] + bias[c];
                float v1 = acc[mi][nj][half * 2 + 1] + bias[c + 1];
                if (EPI == 1) {
                    v0 = 0.5f * v0 * (1.0f + erff(v0 * 0.7071067811865475f));
                    v1 = 0.5f * v1 * (1.0f + erff(v1 * 0.7071067811865475f));
                } else if (EPI == 2) {
                    v0 += res[(size_t)r * M + c];
                    v1 += res[(size_t)r * M + c + 1];
                }
                C[(size_t)r * M + c]     = v0;
                C[(size_t)r * M + c + 1] = v1;
            }
        }
    }
}

// ---------------- LayerNorm ----------------
__global__ void __launch_bounds__(256)
ln_kernel(const float* __restrict__ x, const float* __restrict__ s,
          const float* __restrict__ b, float* __restrict__ y)
{
    const int row = blockIdx.x;
    const int tid = threadIdx.x;
    const float* xr = x + (size_t)row * DIM;

    float v0 = xr[tid];
    float v1 = xr[tid + 256];
    float v2 = xr[tid + 512];

    __shared__ float ssum[256], ssq[256];
    ssum[tid] = v0 + v1 + v2;
    ssq[tid]  = v0 * v0 + v1 * v1 + v2 * v2;
    __syncthreads();
    for (int st = 128; st > 0; st >>= 1) {
        if (tid < st) { ssum[tid] += ssum[tid + st]; ssq[tid] += ssq[tid + st]; }
        __syncthreads();
    }
    const float mean = ssum[0] * (1.0f / DIM);
    const float var  = ssq[0] * (1.0f / DIM) - mean * mean;
    const float inv  = rsqrtf(var + 1e-5f);

    float* yr = y + (size_t)row * DIM;
    yr[tid]       = (v0 - mean) * inv * s[tid]       + b[tid];
    yr[tid + 256] = (v1 - mean) * inv * s[tid + 256] + b[tid + 256];
    yr[tid + 512] = (v2 - mean) * inv * s[tid + 512] + b[tid + 512];
}

// ---------------- Attention ----------------
__global__ void __launch_bounds__(128)
attn_kernel(const float* __restrict__ qkv, const int* __restrict__ routes,
            float* __restrict__ out)
{
    __shared__ float sc[4][200];
    __shared__ int   sidx[4][200];
    __shared__ float qs[4][64];

    const int bh   = blockIdx.x;
    const int b    = bh / NHEAD;
    const int h    = bh % NHEAD;
    const int warp = threadIdx.x >> 5;
    const int lane = threadIdx.x & 31;
    const int s    = blockIdx.y * 4 + warp;
    if (s >= SEQ) return;

    const float* base = qkv + (size_t)b * SEQ * (3 * DIM);
    const float* qp = base + (size_t)s * (3 * DIM) + h * HDIM;
    qs[warp][lane]      = qp[lane];
    qs[warp][lane + 32] = qp[lane + 32];
    __syncwarp();

    const int nk = (s == 0) ? SEQ : TOPK;

    for (int j = lane; j < nk; j += 32) {
        int kidx = (s == 0) ? j : (routes[(s - 1) * TOPK + j] + 1);
        const float* kp = base + (size_t)kidx * (3 * DIM) + DIM + h * HDIM;
        float acc = 0.f;
#pragma unroll
        for (int d = 0; d < HDIM; d++) acc = fmaf(qs[warp][d], kp[d], acc);
        sc[warp][j]   = acc * ATT_SCALE;
        sidx[warp][j] = kidx;
    }
    __syncwarp();

    float m = -1e30f;
    for (int j = lane; j < nk; j += 32) m = fmaxf(m, sc[warp][j]);
#pragma unroll
    for (int o = 16; o; o >>= 1) m = fmaxf(m, __shfl_xor_sync(0xffffffffu, m, o));

    float sum = 0.f;
    for (int j = lane; j < nk; j += 32) {
        float e = expf(sc[warp][j] - m);
        sc[warp][j] = e;
        sum += e;
    }
#pragma unroll
    for (int o = 16; o; o >>= 1) sum += __shfl_xor_sync(0xffffffffu, sum, o);
    __syncwarp();
    const float inv = 1.f / sum;

    float o0 = 0.f, o1 = 0.f;
    for (int j = 0; j < nk; j++) {
        float p = sc[warp][j];
        const float* vp = base + (size_t)sidx[warp][j] * (3 * DIM) + 2 * DIM + h * HDIM;
        o0 = fmaf(p, vp[2 * lane],     o0);
        o1 = fmaf(p, vp[2 * lane + 1], o1);
    }
    size_t ob = ((size_t)(b * SEQ + s)) * DIM + h * HDIM;
    out[ob + 2 * lane]     = o0 * inv;
    out[ob + 2 * lane + 1] = o1 * inv;
}

// ---------------- Patchify ----------------
__global__ void patchify_kernel(const float* __restrict__ x, float* __restrict__ xp)
{
    int idx = blockIdx.x * blockDim.x + threadIdx.x;
    const int total = NROWS_P * DIM;
    if (idx >= total) return;
    int e  = idx % DIM;
    int bp = idx / DIM;
    int p  = bp % NPATCH;
    int b  = bp / NPATCH;
    int c  = e / (PATCH * PATCH);
    int r  = e % (PATCH * PATCH);
    int py = r / PATCH, px = r % PATCH;
    int gy = p / GRID,  gx = p % GRID;
    xp[idx] = x[(((size_t)b * CHN + c) * IMG + gy * PATCH + py) * IMG + gx * PATCH + px];
}

// ---------------- Assemble ----------------
__global__ void assemble_kernel(const float* __restrict__ tok, const float* __restrict__ cls,
                                const float* __restrict__ pos, float* __restrict__ hout)
{
    int idx = blockIdx.x * blockDim.x + threadIdx.x;
    const int total = BATCH * SEQ * DIM;
    if (idx >= total) return;
    int d  = idx % DIM;
    int bs = idx / DIM;
    int s  = bs % SEQ;
    int b  = bs / SEQ;
    float v = (s == 0) ? cls[d] : tok[((size_t)b * NPATCH + (s - 1)) * DIM + d];
    hout[idx] = v + pos[(size_t)s * DIM + d];
}

// ---------------- host launcher ----------------
extern "C" void kernel_launch(void* const* d_in, const int* in_sizes, int n_in,
                              void* d_out, int out_size)
{
    const float* x        = (const float*)d_in[0];
    const float* patch_w  = (const float*)d_in[1];
    const float* patch_b  = (const float*)d_in[2];
    const float* cls_tok  = (const float*)d_in[3];
    const float* pos_emb  = (const float*)d_in[4];
    const float* qkv_w    = (const float*)d_in[5];
    const float* qkv_b    = (const float*)d_in[6];
    const float* proj_w   = (const float*)d_in[7];
    const float* proj_b   = (const float*)d_in[8];
    const float* ln1_s    = (const float*)d_in[9];
    const float* ln1_b    = (const float*)d_in[10];
    const float* ln2_s    = (const float*)d_in[11];
    const float* ln2_b    = (const float*)d_in[12];
    const float* fc1_w    = (const float*)d_in[13];
    const float* fc1_b    = (const float*)d_in[14];
    const float* fc2_w    = (const float*)d_in[15];
    const float* fc2_b    = (const float*)d_in[16];
    const int*   routes   = (const int*)d_in[17];

    float *hbuf, *xn, *qkv, *att, *mlp;
    __nv_bfloat16 *wh, *wl;
    cudaGetSymbolAddress((void**)&hbuf, g_h);
    cudaGetSymbolAddress((void**)&xn,   g_xn);
    cudaGetSymbolAddress((void**)&qkv,  g_qkv);
    cudaGetSymbolAddress((void**)&att,  g_att);
    cudaGetSymbolAddress((void**)&mlp,  g_mlp);
    cudaGetSymbolAddress((void**)&wh,   g_wh);
    cudaGetSymbolAddress((void**)&wl,   g_wl);

    const int SMEM = 2 * 30720;   // 61440
    cudaFuncSetAttribute(hgemm<0>, cudaFuncAttributeMaxDynamicSharedMemorySize, SMEM);
    cudaFuncSetAttribute(hgemm<1>, cudaFuncAttributeMaxDynamicSharedMemorySize, SMEM);
    cudaFuncSetAttribute(hgemm<2>, cudaFuncAttributeMaxDynamicSharedMemorySize, SMEM);

    // ---- pre-convert all weights to bf16 hi/lo ----
    {
        struct { const float* src; int off; int n; } cv[5] = {
            {patch_w, OFF_PATCH, NW_PATCH},
            {qkv_w,   OFF_QKV,   NW_QKV},
            {proj_w,  OFF_PROJ,  NW_PROJ},
            {fc1_w,   OFF_FC1,   NW_FC1},
            {fc2_w,   OFF_FC2,   NW_FC2},
        };
        for (int i = 0; i < 5; i++) {
            int n4 = cv[i].n / 4;
            cvt_weights<<<(n4 + 255) / 256, 256>>>(cv[i].src, wh + cv[i].off, wl + cv[i].off, n4);
        }
    }

    const int rt = 13;  // ceil(1576/128)

    // patch embed
    {
        int tot = NROWS_P * DIM;
        patchify_kernel<<<(tot + 255) / 256, 256>>>(x, mlp);
        hgemm<0><<<dim3(DIM / 64, rt), 256, SMEM>>>(mlp, wh + OFF_PATCH, wl + OFF_PATCH,
                                                    patch_b, nullptr, att, NROWS_P, DIM, DIM);
        int tot2 = BATCH * SEQ * DIM;
        assemble_kernel<<<(tot2 + 255) / 256, 256>>>(att, cls_tok, pos_emb, hbuf);
    }

    for (int l = 0; l < NLAYER; l++) {
        const size_t oq  = OFF_QKV  + (size_t)l * 3 * DIM * DIM;
        const size_t op  = OFF_PROJ + (size_t)l * DIM * DIM;
        const size_t of1 = OFF_FC1  + (size_t)l * MLPDIM * DIM;
        const size_t of2 = OFF_FC2  + (size_t)l * DIM * MLPDIM;
        const float* qb  = qkv_b  + (size_t)l * 3 * DIM;
        const float* pb  = proj_b + (size_t)l * DIM;
        const float* f1b = fc1_b  + (size_t)l * MLPDIM;
        const float* f2b = fc2_b  + (size_t)l * DIM;

        ln_kernel<<<NROWS, 256>>>(hbuf, ln1_s + (size_t)l * DIM, ln1_b + (size_t)l * DIM, xn);
        hgemm<0><<<dim3(3 * DIM / 64, rt), 256, SMEM>>>(xn, wh + oq, wl + oq, qb, nullptr,
                                                        qkv, NROWS, DIM, 3 * DIM);
        attn_kernel<<<dim3(BATCH * NHEAD, (SEQ + 3) / 4), 128>>>(qkv, routes, att);
        hgemm<2><<<dim3(DIM / 64, rt), 256, SMEM>>>(att, wh + op, wl + op, pb, hbuf,
                                                    hbuf, NROWS, DIM, DIM);
        ln_kernel<<<NROWS, 256>>>(hbuf, ln2_s + (size_t)l * DIM, ln2_b + (size_t)l * DIM, xn);
        hgemm<1><<<dim3(MLPDIM / 64, rt), 256, SMEM>>>(xn, wh + of1, wl + of1, f1b, nullptr,
                                                       mlp, NROWS, DIM, MLPDIM);
        float* outp = (l == NLAYER - 1) ? (float*)d_out : hbuf;
        hgemm<2><<<dim3(DIM / 64, rt), 256, SMEM>>>(mlp, wh + of2, wl + of2, f2b, hbuf,
                                                    outp, NROWS, MLPDIM, DIM);
    }
}

// round 4
// speedup vs baseline: 2.4374x; 1.2123x over previous
#include <cuda_runtime.h>
#include <cuda_bf16.h>
#include <math.h>
#include <stdint.h>

// ---------------- problem constants ----------------
#define BATCH 8
#define CHN 3
#define IMG 224
#define PATCH 16
#define GRID 14
#define NPATCH 196
#define SEQ 197
#define DIM 768
#define NHEAD 12
#define HDIM 64
#define NLAYER 12
#define TOPK 32
#define MLPDIM 3072
#define ATT_SCALE 0.125f

#define NROWS (BATCH*SEQ)           // 1576
#define NROWS_P (BATCH*NPATCH)      // 1568

// weight-buffer element offsets (concatenated bf16 hi/lo arrays)
#define NW_PATCH (DIM*DIM)
#define NW_QKV   (NLAYER*3*DIM*DIM)
#define NW_PROJ  (NLAYER*DIM*DIM)
#define NW_FC1   (NLAYER*MLPDIM*DIM)
#define NW_FC2   (NLAYER*DIM*MLPDIM)
#define OFF_PATCH 0
#define OFF_QKV   (OFF_PATCH + NW_PATCH)
#define OFF_PROJ  (OFF_QKV + NW_QKV)
#define OFF_FC1   (OFF_PROJ + NW_PROJ)
#define OFF_FC2   (OFF_FC1 + NW_FC1)
#define NW_TOTAL  (OFF_FC2 + NW_FC2)

// ---------------- scratch ----------------
__device__ float g_h  [BATCH*SEQ*DIM];
__device__ float g_qkv[BATCH*SEQ*3*DIM];          // also reused for patch-token fp32 out
__device__ __nv_bfloat16 g_xnh [BATCH*SEQ*DIM];
__device__ __nv_bfloat16 g_xnl [BATCH*SEQ*DIM];
__device__ __nv_bfloat16 g_atth[BATCH*SEQ*DIM];
__device__ __nv_bfloat16 g_attl[BATCH*SEQ*DIM];
__device__ __nv_bfloat16 g_mlph[BATCH*SEQ*MLPDIM];
__device__ __nv_bfloat16 g_mlpl[BATCH*SEQ*MLPDIM];
__device__ __nv_bfloat16 g_wh[NW_TOTAL];
__device__ __nv_bfloat16 g_wl[NW_TOTAL];

// ---------------- helpers ----------------
__device__ __forceinline__ uint32_t smem_u32(const void* p) {
    uint32_t a;
    asm("{ .reg .u64 t; cvta.to.shared.u64 t, %1; cvt.u32.u64 %0, t; }" : "=r"(a) : "l"(p));
    return a;
}
__device__ __forceinline__ uint32_t pack_bf16(__nv_bfloat16 a, __nv_bfloat16 b) {
    return (uint32_t)__bfloat16_as_ushort(a) | ((uint32_t)__bfloat16_as_ushort(b) << 16);
}
__device__ __forceinline__ void split1(float v, __nv_bfloat16& h, __nv_bfloat16& l) {
    h = __float2bfloat16(v);
    l = __float2bfloat16(v - __bfloat162float(h));
}
__device__ __forceinline__ void ldmx4(uint32_t& r0, uint32_t& r1, uint32_t& r2, uint32_t& r3,
                                      uint32_t addr) {
    asm volatile("ldmatrix.sync.aligned.m8n8.x4.shared.b16 {%0,%1,%2,%3}, [%4];"
                 : "=r"(r0), "=r"(r1), "=r"(r2), "=r"(r3) : "r"(addr));
}
__device__ __forceinline__ void mma16816(float* d, const uint32_t* a, uint32_t b0, uint32_t b1) {
    asm volatile(
        "mma.sync.aligned.m16n8k16.row.col.f32.bf16.bf16.f32 "
        "{%0,%1,%2,%3},{%4,%5,%6,%7},{%8,%9},{%0,%1,%2,%3};"
        : "+f"(d[0]), "+f"(d[1]), "+f"(d[2]), "+f"(d[3])
        : "r"(a[0]), "r"(a[1]), "r"(a[2]), "r"(a[3]), "r"(b0), "r"(b1));
}
#define CP16(dst, src, sz) \
    asm volatile("cp.async.cg.shared.global [%0], [%1], 16, %2;" \
                 :: "r"(dst), "l"(src), "r"(sz))
#define CP_COMMIT() asm volatile("cp.async.commit_group;")
template<int N> __device__ __forceinline__ void cp_wait() {
    asm volatile("cp.async.wait_group %0;" :: "n"(N));
}

// ---------------- weight pre-conversion ----------------
__global__ void __launch_bounds__(256)
cvt_weights(const float* __restrict__ src, __nv_bfloat16* __restrict__ hi,
            __nv_bfloat16* __restrict__ lo, int n4)
{
    int i = blockIdx.x * blockDim.x + threadIdx.x;
    if (i >= n4) return;
    float4 f = reinterpret_cast<const float4*>(src)[i];
    __nv_bfloat16 h0, h1, h2, h3, l0, l1, l2, l3;
    split1(f.x, h0, l0); split1(f.y, h1, l1);
    split1(f.z, h2, l2); split1(f.w, h3, l3);
    uint2 H, L;
    H.x = pack_bf16(h0, h1); H.y = pack_bf16(h2, h3);
    L.x = pack_bf16(l0, l1); L.y = pack_bf16(l2, l3);
    reinterpret_cast<uint2*>(hi)[i] = H;
    reinterpret_cast<uint2*>(lo)[i] = L;
}

// ---------------- HMMA GEMM (bf16x3, cp.async 3-stage) ----------------
// C[n,m] = sum_k A[n,k]*W[m,k] + bias[m] (+epilogue)
// A and W pre-split bf16 hi/lo. BN=64, BK=32. Warp tile 32x32.
// BM=128 -> 256 thr (8 warps 4x2);  BM=64 -> 128 thr (4 warps 2x2).
// EPI: 0 bias->fp32, 1 bias+GELU->bf16 hi/lo, 2 bias+residual->fp32
template<int BM, int EPI>
__global__ void __launch_bounds__(BM*2)
hgemm(const __nv_bfloat16* __restrict__ Ah, const __nv_bfloat16* __restrict__ Al,
      const __nv_bfloat16* __restrict__ Wh, const __nv_bfloat16* __restrict__ Wl,
      const float* __restrict__ bias, const float* __restrict__ res,
      float* __restrict__ C, __nv_bfloat16* __restrict__ Ch, __nv_bfloat16* __restrict__ Cl,
      int Nrows, int K, int M)
{
    constexpr int BN = 64, BK = 32;
    constexpr int THREADS = BM * 2;
    constexpr int MW = BM / 32;             // m-warps
    constexpr int ASTB = 80;                // 64B data + 16B pad per row
    constexpr int ABYTES = BM * ASTB;
    constexpr int BBYTES = BN * ASTB;
    constexpr int STAGE = 2 * ABYTES + 2 * BBYTES;
    constexpr int O_AH = 0, O_AL = ABYTES, O_BH = 2 * ABYTES, O_BL = 2 * ABYTES + BBYTES;

    extern __shared__ char sm_[];
    const uint32_t sbase = smem_u32(sm_);

    const int tid  = threadIdx.x;
    const int lane = tid & 31;
    const int wid  = tid >> 5;
    const int wm   = wid % MW;
    const int wn   = wid / MW;
    const int row0 = blockIdx.y * BM;
    const int col0 = blockIdx.x * BN;

    // cp.async staging descriptors
    // A: BM*4 16B-units (per hi and lo); 2 per thread
    int arow[2], asz[2];
    uint32_t adst[2];
    const __nv_bfloat16 *ahs[2], *als[2];
#pragma unroll
    for (int i = 0; i < 2; i++) {
        int u = tid + i * THREADS;
        int r = u >> 2, q = u & 3;
        arow[i] = r;
        asz[i]  = (row0 + r < Nrows) ? 16 : 0;
        adst[i] = (uint32_t)(r * ASTB + q * 16);
        ahs[i]  = Ah + (size_t)(row0 + r) * K + q * 8;
        als[i]  = Al + (size_t)(row0 + r) * K + q * 8;
    }
    // B: 256 16B-units; 256/THREADS per thread
    constexpr int BU = 256 / THREADS;
    uint32_t bdst[BU];
    const __nv_bfloat16 *bhs[BU], *bls[BU];
#pragma unroll
    for (int i = 0; i < BU; i++) {
        int u = tid + i * THREADS;
        int r = u >> 2, q = u & 3;
        bdst[i] = (uint32_t)(r * ASTB + q * 16);
        bhs[i]  = Wh + (size_t)(col0 + r) * K + q * 8;
        bls[i]  = Wl + (size_t)(col0 + r) * K + q * 8;
    }

    // ldmatrix offsets within a stage
    uint32_t aoff[2], boff[2];
#pragma unroll
    for (int mi = 0; mi < 2; mi++)
        aoff[mi] = (uint32_t)((wm * 32 + mi * 16 + (lane & 15)) * ASTB + (lane >> 4) * 16);
#pragma unroll
    for (int nj2 = 0; nj2 < 2; nj2++)
        boff[nj2] = (uint32_t)((wn * 32 + nj2 * 16 + (lane & 7) + ((lane >> 4) << 3)) * ASTB
                               + ((lane >> 3) & 1) * 16);

    float acc[2][4][4];
#pragma unroll
    for (int mi = 0; mi < 2; mi++)
#pragma unroll
        for (int nj = 0; nj < 4; nj++)
#pragma unroll
            for (int v = 0; v < 4; v++) acc[mi][nj][v] = 0.f;

    const int KT = K / BK;

    auto load_stage = [&](int s, int k0) {
        const uint32_t sb = sbase + (uint32_t)(s * STAGE);
#pragma unroll
        for (int i = 0; i < 2; i++) {
            CP16(sb + O_AH + adst[i], ahs[i] + k0, asz[i]);
            CP16(sb + O_AL + adst[i], als[i] + k0, asz[i]);
        }
#pragma unroll
        for (int i = 0; i < BU; i++) {
            CP16(sb + O_BH + bdst[i], bhs[i] + k0, 16);
            CP16(sb + O_BL + bdst[i], bls[i] + k0, 16);
        }
    };

    load_stage(0, 0);  CP_COMMIT();
    load_stage(1, BK); CP_COMMIT();

    for (int kt = 0; kt < KT; kt++) {
        cp_wait<1>();
        __syncthreads();
        if (kt + 2 < KT) load_stage((kt + 2) % 3, (kt + 2) * BK);
        CP_COMMIT();

        const uint32_t sb = sbase + (uint32_t)((kt % 3) * STAGE);
#pragma unroll
        for (int k16 = 0; k16 < 2; k16++) {
            const uint32_t kb = (uint32_t)(k16 * 32);
            uint32_t ah[2][4], al[2][4], bh[2][4], bl[2][4];
#pragma unroll
            for (int mi = 0; mi < 2; mi++)
                ldmx4(ah[mi][0], ah[mi][1], ah[mi][2], ah[mi][3], sb + O_AH + aoff[mi] + kb);
#pragma unroll
            for (int nj2 = 0; nj2 < 2; nj2++)
                ldmx4(bh[nj2][0], bh[nj2][1], bh[nj2][2], bh[nj2][3], sb + O_BH + boff[nj2] + kb);
            // hi*hi
#pragma unroll
            for (int mi = 0; mi < 2; mi++)
#pragma unroll
                for (int nj = 0; nj < 4; nj++)
                    mma16816(acc[mi][nj], ah[mi],
                             bh[nj >> 1][(nj & 1) * 2], bh[nj >> 1][(nj & 1) * 2 + 1]);
            // hi*lo
#pragma unroll
            for (int nj2 = 0; nj2 < 2; nj2++)
                ldmx4(bl[nj2][0], bl[nj2][1], bl[nj2][2], bl[nj2][3], sb + O_BL + boff[nj2] + kb);
#pragma unroll
            for (int mi = 0; mi < 2; mi++)
#pragma unroll
                for (int nj = 0; nj < 4; nj++)
                    mma16816(acc[mi][nj], ah[mi],
                             bl[nj >> 1][(nj & 1) * 2], bl[nj >> 1][(nj & 1) * 2 + 1]);
            // lo*hi
#pragma unroll
            for (int mi = 0; mi < 2; mi++)
                ldmx4(al[mi][0], al[mi][1], al[mi][2], al[mi][3], sb + O_AL + aoff[mi] + kb);
#pragma unroll
            for (int mi = 0; mi < 2; mi++)
#pragma unroll
                for (int nj = 0; nj < 4; nj++)
                    mma16816(acc[mi][nj], al[mi],
                             bh[nj >> 1][(nj & 1) * 2], bh[nj >> 1][(nj & 1) * 2 + 1]);
        }
    }

    // ---- epilogue ----
    const int g  = lane >> 2;
    const int tg = lane & 3;
#pragma unroll
    for (int mi = 0; mi < 2; mi++) {
#pragma unroll
        for (int half = 0; half < 2; half++) {
            const int r = row0 + wm * 32 + mi * 16 + g + half * 8;
            if (r >= Nrows) continue;
#pragma unroll
            for (int nj = 0; nj < 4; nj++) {
                const int c = col0 + wn * 32 + nj * 8 + tg * 2;
                float v0 = acc[mi][nj][half * 2 + 0] + bias[c];
                float v1 = acc[mi][nj][half * 2 + 1] + bias[c + 1];
                if (EPI == 1) {
                    v0 = 0.5f * v0 * (1.0f + erff(v0 * 0.7071067811865475f));
                    v1 = 0.5f * v1 * (1.0f + erff(v1 * 0.7071067811865475f));
                    __nv_bfloat16 h0, l0, h1, l1;
                    split1(v0, h0, l0); split1(v1, h1, l1);
                    *reinterpret_cast<uint32_t*>(Ch + (size_t)r * M + c) = pack_bf16(h0, h1);
                    *reinterpret_cast<uint32_t*>(Cl + (size_t)r * M + c) = pack_bf16(l0, l1);
                } else {
                    if (EPI == 2) {
                        v0 += res[(size_t)r * M + c];
                        v1 += res[(size_t)r * M + c + 1];
                    }
                    C[(size_t)r * M + c]     = v0;
                    C[(size_t)r * M + c + 1] = v1;
                }
            }
        }
    }
}

// ---------------- LayerNorm -> bf16 hi/lo ----------------
__global__ void __launch_bounds__(256)
ln_kernel(const float* __restrict__ x, const float* __restrict__ s,
          const float* __restrict__ b, __nv_bfloat16* __restrict__ yh,
          __nv_bfloat16* __restrict__ yl)
{
    const int row = blockIdx.x;
    const int tid = threadIdx.x;
    const float* xr = x + (size_t)row * DIM;

    float v0 = xr[tid];
    float v1 = xr[tid + 256];
    float v2 = xr[tid + 512];

    __shared__ float ssum[256], ssq[256];
    ssum[tid] = v0 + v1 + v2;
    ssq[tid]  = v0 * v0 + v1 * v1 + v2 * v2;
    __syncthreads();
    for (int st = 128; st > 0; st >>= 1) {
        if (tid < st) { ssum[tid] += ssum[tid + st]; ssq[tid] += ssq[tid + st]; }
        __syncthreads();
    }
    const float mean = ssum[0] * (1.0f / DIM);
    const float var  = ssq[0] * (1.0f / DIM) - mean * mean;
    const float inv  = rsqrtf(var + 1e-5f);

    __nv_bfloat16 h, l;
    size_t o = (size_t)row * DIM;
    float y0 = (v0 - mean) * inv * s[tid]       + b[tid];
    float y1 = (v1 - mean) * inv * s[tid + 256] + b[tid + 256];
    float y2 = (v2 - mean) * inv * s[tid + 512] + b[tid + 512];
    split1(y0, h, l); yh[o + tid]       = h; yl[o + tid]       = l;
    split1(y1, h, l); yh[o + tid + 256] = h; yl[o + tid + 256] = l;
    split1(y2, h, l); yh[o + tid + 512] = h; yl[o + tid + 512] = l;
}

// ---------------- Attention -> bf16 hi/lo ----------------
__global__ void __launch_bounds__(128)
attn_kernel(const float* __restrict__ qkv, const int* __restrict__ routes,
            __nv_bfloat16* __restrict__ outh, __nv_bfloat16* __restrict__ outl)
{
    __shared__ float sc[4][200];
    __shared__ int   sidx[4][200];
    __shared__ float qs[4][64];

    const int bh   = blockIdx.x;
    const int b    = bh / NHEAD;
    const int h    = bh % NHEAD;
    const int warp = threadIdx.x >> 5;
    const int lane = threadIdx.x & 31;
    const int s    = blockIdx.y * 4 + warp;
    if (s >= SEQ) return;

    const float* base = qkv + (size_t)b * SEQ * (3 * DIM);
    const float* qp = base + (size_t)s * (3 * DIM) + h * HDIM;
    qs[warp][lane]      = qp[lane];
    qs[warp][lane + 32] = qp[lane + 32];
    __syncwarp();

    const int nk = (s == 0) ? SEQ : TOPK;

    for (int j = lane; j < nk; j += 32) {
        int kidx = (s == 0) ? j : (routes[(s - 1) * TOPK + j] + 1);
        const float* kp = base + (size_t)kidx * (3 * DIM) + DIM + h * HDIM;
        float acc = 0.f;
#pragma unroll
        for (int d = 0; d < HDIM; d++) acc = fmaf(qs[warp][d], kp[d], acc);
        sc[warp][j]   = acc * ATT_SCALE;
        sidx[warp][j] = kidx;
    }
    __syncwarp();

    float m = -1e30f;
    for (int j = lane; j < nk; j += 32) m = fmaxf(m, sc[warp][j]);
#pragma unroll
    for (int o = 16; o; o >>= 1) m = fmaxf(m, __shfl_xor_sync(0xffffffffu, m, o));

    float sum = 0.f;
    for (int j = lane; j < nk; j += 32) {
        float e = expf(sc[warp][j] - m);
        sc[warp][j] = e;
        sum += e;
    }
#pragma unroll
    for (int o = 16; o; o >>= 1) sum += __shfl_xor_sync(0xffffffffu, sum, o);
    __syncwarp();
    const float inv = 1.f / sum;

    float o0 = 0.f, o1 = 0.f;
    for (int j = 0; j < nk; j++) {
        float p = sc[warp][j];
        const float* vp = base + (size_t)sidx[warp][j] * (3 * DIM) + 2 * DIM + h * HDIM;
        o0 = fmaf(p, vp[2 * lane],     o0);
        o1 = fmaf(p, vp[2 * lane + 1], o1);
    }
    size_t ob = ((size_t)(b * SEQ + s)) * DIM + h * HDIM;
    __nv_bfloat16 h0, l0, h1, l1;
    split1(o0 * inv, h0, l0);
    split1(o1 * inv, h1, l1);
    *reinterpret_cast<uint32_t*>(outh + ob + 2 * lane) = pack_bf16(h0, h1);
    *reinterpret_cast<uint32_t*>(outl + ob + 2 * lane) = pack_bf16(l0, l1);
}

// ---------------- Patchify -> bf16 hi/lo ----------------
__global__ void patchify_kernel(const float* __restrict__ x,
                                __nv_bfloat16* __restrict__ xph, __nv_bfloat16* __restrict__ xpl)
{
    int idx = blockIdx.x * blockDim.x + threadIdx.x;
    const int total = NROWS_P * DIM;
    if (idx >= total) return;
    int e  = idx % DIM;
    int bp = idx / DIM;
    int p  = bp % NPATCH;
    int b  = bp / NPATCH;
    int c  = e / (PATCH * PATCH);
    int r  = e % (PATCH * PATCH);
    int py = r / PATCH, px = r % PATCH;
    int gy = p / GRID,  gx = p % GRID;
    float v = x[(((size_t)b * CHN + c) * IMG + gy * PATCH + py) * IMG + gx * PATCH + px];
    __nv_bfloat16 h, l;
    split1(v, h, l);
    xph[idx] = h;
    xpl[idx] = l;
}

// ---------------- Assemble ----------------
__global__ void assemble_kernel(const float* __restrict__ tok, const float* __restrict__ cls,
                                const float* __restrict__ pos, float* __restrict__ hout)
{
    int idx = blockIdx.x * blockDim.x + threadIdx.x;
    const int total = BATCH * SEQ * DIM;
    if (idx >= total) return;
    int d  = idx % DIM;
    int bs = idx / DIM;
    int s  = bs % SEQ;
    int b  = bs / SEQ;
    float v = (s == 0) ? cls[d] : tok[((size_t)b * NPATCH + (s - 1)) * DIM + d];
    hout[idx] = v + pos[(size_t)s * DIM + d];
}

// ---------------- host launcher ----------------
extern "C" void kernel_launch(void* const* d_in, const int* in_sizes, int n_in,
                              void* d_out, int out_size)
{
    const float* x        = (const float*)d_in[0];
    const float* patch_w  = (const float*)d_in[1];
    const float* patch_b  = (const float*)d_in[2];
    const float* cls_tok  = (const float*)d_in[3];
    const float* pos_emb  = (const float*)d_in[4];
    const float* qkv_w    = (const float*)d_in[5];
    const float* qkv_b    = (const float*)d_in[6];
    const float* proj_w   = (const float*)d_in[7];
    const float* proj_b   = (const float*)d_in[8];
    const float* ln1_s    = (const float*)d_in[9];
    const float* ln1_b    = (const float*)d_in[10];
    const float* ln2_s    = (const float*)d_in[11];
    const float* ln2_b    = (const float*)d_in[12];
    const float* fc1_w    = (const float*)d_in[13];
    const float* fc1_b    = (const float*)d_in[14];
    const float* fc2_w    = (const float*)d_in[15];
    const float* fc2_b    = (const float*)d_in[16];
    const int*   routes   = (const int*)d_in[17];

    float *hbuf, *qkv;
    __nv_bfloat16 *xnh, *xnl, *atth, *attl, *mlph, *mlpl, *wh, *wl;
    cudaGetSymbolAddress((void**)&hbuf, g_h);
    cudaGetSymbolAddress((void**)&qkv,  g_qkv);
    cudaGetSymbolAddress((void**)&xnh,  g_xnh);
    cudaGetSymbolAddress((void**)&xnl,  g_xnl);
    cudaGetSymbolAddress((void**)&atth, g_atth);
    cudaGetSymbolAddress((void**)&attl, g_attl);
    cudaGetSymbolAddress((void**)&mlph, g_mlph);
    cudaGetSymbolAddress((void**)&mlpl, g_mlpl);
    cudaGetSymbolAddress((void**)&wh,   g_wh);
    cudaGetSymbolAddress((void**)&wl,   g_wl);

    const int SMEM128 = 3 * 30720;  // 92160
    const int SMEM64  = 3 * 20480;  // 61440
    cudaFuncSetAttribute(hgemm<128, 0>, cudaFuncAttributeMaxDynamicSharedMemorySize, SMEM128);
    cudaFuncSetAttribute(hgemm<128, 1>, cudaFuncAttributeMaxDynamicSharedMemorySize, SMEM128);
    cudaFuncSetAttribute(hgemm<64, 2>,  cudaFuncAttributeMaxDynamicSharedMemorySize, SMEM64);

    // ---- one-time weight split ----
    {
        struct { const float* src; int off; int n; } cv[5] = {
            {patch_w, OFF_PATCH, NW_PATCH},
            {qkv_w,   OFF_QKV,   NW_QKV},
            {proj_w,  OFF_PROJ,  NW_PROJ},
            {fc1_w,   OFF_FC1,   NW_FC1},
            {fc2_w,   OFF_FC2,   NW_FC2},
        };
        for (int i = 0; i < 5; i++) {
            int n4 = cv[i].n / 4;
            cvt_weights<<<(n4 + 255) / 256, 256>>>(cv[i].src, wh + cv[i].off, wl + cv[i].off, n4);
        }
    }

    const int rt128 = 13;                       // ceil(1576/128)
    const int rt64  = (NROWS + 63) / 64;        // 25

    // patch embed: patchify -> mlp hi/lo (reuse), GEMM -> qkv buf (fp32), assemble -> h
    {
        int tot = NROWS_P * DIM;
        patchify_kernel<<<(tot + 255) / 256, 256>>>(x, mlph, mlpl);
        hgemm<128, 0><<<dim3(DIM / 64, rt128), 256, SMEM128>>>(
            mlph, mlpl, wh + OFF_PATCH, wl + OFF_PATCH, patch_b, nullptr,
            qkv, nullptr, nullptr, NROWS_P, DIM, DIM);
        int tot2 = BATCH * SEQ * DIM;
        assemble_kernel<<<(tot2 + 255) / 256, 256>>>(qkv, cls_tok, pos_emb, hbuf);
    }

    for (int l = 0; l < NLAYER; l++) {
        const size_t oq  = OFF_QKV  + (size_t)l * 3 * DIM * DIM;
        const size_t op  = OFF_PROJ + (size_t)l * DIM * DIM;
        const size_t of1 = OFF_FC1  + (size_t)l * MLPDIM * DIM;
        const size_t of2 = OFF_FC2  + (size_t)l * DIM * MLPDIM;
        const float* qb  = qkv_b  + (size_t)l * 3 * DIM;
        const float* pb  = proj_b + (size_t)l * DIM;
        const float* f1b = fc1_b  + (size_t)l * MLPDIM;
        const float* f2b = fc2_b  + (size_t)l * DIM;

        ln_kernel<<<NROWS, 256>>>(hbuf, ln1_s + (size_t)l * DIM, ln1_b + (size_t)l * DIM,
                                  xnh, xnl);
        hgemm<128, 0><<<dim3(3 * DIM / 64, rt128), 256, SMEM128>>>(
            xnh, xnl, wh + oq, wl + oq, qb, nullptr,
            qkv, nullptr, nullptr, NROWS, DIM, 3 * DIM);
        attn_kernel<<<dim3(BATCH * NHEAD, (SEQ + 3) / 4), 128>>>(qkv, routes, atth, attl);
        hgemm<64, 2><<<dim3(DIM / 64, rt64), 128, SMEM64>>>(
            atth, attl, wh + op, wl + op, pb, hbuf,
            hbuf, nullptr, nullptr, NROWS, DIM, DIM);
        ln_kernel<<<NROWS, 256>>>(hbuf, ln2_s + (size_t)l * DIM, ln2_b + (size_t)l * DIM,
                                  xnh, xnl);
        hgemm<128, 1><<<dim3(MLPDIM / 64, rt128), 256, SMEM128>>>(
            xnh, xnl, wh + of1, wl + of1, f1b, nullptr,
            nullptr, mlph, mlpl, NROWS, DIM, MLPDIM);
        float* outp = (l == NLAYER - 1) ? (float*)d_out : hbuf;
        hgemm<64, 2><<<dim3(DIM / 64, rt64), 128, SMEM64>>>(
            mlph, mlpl, wh + of2, wl + of2, f2b, hbuf,
            outp, nullptr, nullptr, NROWS, MLPDIM, DIM);
    }
}

// round 5
// speedup vs baseline: 2.4506x; 1.0054x over previous
#include <cuda_runtime.h>
#include <cuda_bf16.h>
#include <math.h>
#include <stdint.h>

// ---------------- problem constants ----------------
#define BATCH 8
#define CHN 3
#define IMG 224
#define PATCH 16
#define GRID 14
#define NPATCH 196
#define SEQ 197
#define DIM 768
#define NHEAD 12
#define HDIM 64
#define NLAYER 12
#define TOPK 32
#define MLPDIM 3072
#define ATT_SCALE 0.125f

#define NROWS (BATCH*SEQ)           // 1576
#define NROWS_P (BATCH*NPATCH)      // 1568

#define NW_PATCH (DIM*DIM)
#define NW_QKV   (NLAYER*3*DIM*DIM)
#define NW_PROJ  (NLAYER*DIM*DIM)
#define NW_FC1   (NLAYER*MLPDIM*DIM)
#define NW_FC2   (NLAYER*DIM*MLPDIM)
#define OFF_PATCH 0
#define OFF_QKV   (OFF_PATCH + NW_PATCH)
#define OFF_PROJ  (OFF_QKV + NW_QKV)
#define OFF_FC1   (OFF_PROJ + NW_PROJ)
#define OFF_FC2   (OFF_FC1 + NW_FC1)
#define NW_TOTAL  (OFF_FC2 + NW_FC2)

// ---------------- scratch ----------------
__device__ float g_h  [BATCH*SEQ*DIM];
__device__ float g_qkv[BATCH*SEQ*3*DIM];
__device__ __nv_bfloat16 g_xnh [BATCH*SEQ*DIM];
__device__ __nv_bfloat16 g_xnl [BATCH*SEQ*DIM];
__device__ __nv_bfloat16 g_atth[BATCH*SEQ*DIM];
__device__ __nv_bfloat16 g_attl[BATCH*SEQ*DIM];
__device__ __nv_bfloat16 g_mlph[BATCH*SEQ*MLPDIM];
__device__ __nv_bfloat16 g_mlpl[BATCH*SEQ*MLPDIM];
__device__ __nv_bfloat16 g_wh[NW_TOTAL];
__device__ __nv_bfloat16 g_wl[NW_TOTAL];

// ---------------- helpers ----------------
__device__ __forceinline__ uint32_t smem_u32(const void* p) {
    uint32_t a;
    asm("{ .reg .u64 t; cvta.to.shared.u64 t, %1; cvt.u32.u64 %0, t; }" : "=r"(a) : "l"(p));
    return a;
}
__device__ __forceinline__ uint32_t pack_bf16(__nv_bfloat16 a, __nv_bfloat16 b) {
    return (uint32_t)__bfloat16_as_ushort(a) | ((uint32_t)__bfloat16_as_ushort(b) << 16);
}
__device__ __forceinline__ void split1(float v, __nv_bfloat16& h, __nv_bfloat16& l) {
    h = __float2bfloat16(v);
    l = __float2bfloat16(v - __bfloat162float(h));
}
__device__ __forceinline__ void ldmx4(uint32_t& r0, uint32_t& r1, uint32_t& r2, uint32_t& r3,
                                      uint32_t addr) {
    asm volatile("ldmatrix.sync.aligned.m8n8.x4.shared.b16 {%0,%1,%2,%3}, [%4];"
                 : "=r"(r0), "=r"(r1), "=r"(r2), "=r"(r3) : "r"(addr));
}
__device__ __forceinline__ void mma16816(float* d, const uint32_t* a, uint32_t b0, uint32_t b1) {
    asm volatile(
        "mma.sync.aligned.m16n8k16.row.col.f32.bf16.bf16.f32 "
        "{%0,%1,%2,%3},{%4,%5,%6,%7},{%8,%9},{%0,%1,%2,%3};"
        : "+f"(d[0]), "+f"(d[1]), "+f"(d[2]), "+f"(d[3])
        : "r"(a[0]), "r"(a[1]), "r"(a[2]), "r"(a[3]), "r"(b0), "r"(b1));
}
#define CP16(dst, src, sz) \
    asm volatile("cp.async.cg.shared.global [%0], [%1], 16, %2;" \
                 :: "r"(dst), "l"(src), "r"(sz))
#define CP_COMMIT() asm volatile("cp.async.commit_group;")
template<int N> __device__ __forceinline__ void cp_wait() {
    asm volatile("cp.async.wait_group %0;" :: "n"(N));
}

// ---------------- weight pre-conversion ----------------
__global__ void __launch_bounds__(256)
cvt_weights(const float* __restrict__ src, __nv_bfloat16* __restrict__ hi,
            __nv_bfloat16* __restrict__ lo, int n4)
{
    int i = blockIdx.x * blockDim.x + threadIdx.x;
    if (i >= n4) return;
    float4 f = reinterpret_cast<const float4*>(src)[i];
    __nv_bfloat16 h0, h1, h2, h3, l0, l1, l2, l3;
    split1(f.x, h0, l0); split1(f.y, h1, l1);
    split1(f.z, h2, l2); split1(f.w, h3, l3);
    uint2 H, L;
    H.x = pack_bf16(h0, h1); H.y = pack_bf16(h2, h3);
    L.x = pack_bf16(l0, l1); L.y = pack_bf16(l2, l3);
    reinterpret_cast<uint2*>(hi)[i] = H;
    reinterpret_cast<uint2*>(lo)[i] = L;
}

// ---------------- HMMA GEMM (bf16x3, cp.async 3-stage, warp tile 32x64) ----------------
// C[n,m] = sum_k A[n,k]*W[m,k] + bias[m] (+epilogue)
// BN=128, BK=32. BM=128 -> 256 thr (8 warps, 4m x 2n). BM=64 -> 128 thr (4 warps, 2m x 2n).
// EPI: 0 bias->fp32, 1 bias+GELU->bf16 hi/lo, 2 bias+residual->fp32
template<int BM, int EPI>
__global__ void __launch_bounds__(BM*2)
hgemm(const __nv_bfloat16* __restrict__ Ah, const __nv_bfloat16* __restrict__ Al,
      const __nv_bfloat16* __restrict__ Wh, const __nv_bfloat16* __restrict__ Wl,
      const float* __restrict__ bias, const float* __restrict__ res,
      float* __restrict__ C, __nv_bfloat16* __restrict__ Ch, __nv_bfloat16* __restrict__ Cl,
      int Nrows, int K, int M)
{
    constexpr int BN = 128, BK = 32;
    constexpr int THREADS = BM * 2;
    constexpr int MW = BM / 32;             // m-warps (4 or 2)
    constexpr int ASTB = 80;                // 64B data + 16B pad -> conflict-free
    constexpr int ABYTES = BM * ASTB;
    constexpr int BBYTES = BN * ASTB;
    constexpr int STAGE = 2 * ABYTES + 2 * BBYTES;
    constexpr int O_AH = 0, O_AL = ABYTES, O_BH = 2 * ABYTES, O_BL = 2 * ABYTES + BBYTES;

    extern __shared__ char sm_[];
    const uint32_t sbase = smem_u32(sm_);

    const int tid  = threadIdx.x;
    const int lane = tid & 31;
    const int wid  = tid >> 5;
    const int wm   = wid % MW;
    const int wn   = wid / MW;              // 0..1, col offset 64*wn
    const int row0 = blockIdx.y * BM;
    const int col0 = blockIdx.x * BN;

    // A staging: BM*4 16B-units, 2 per thread
    int asz[2];
    uint32_t adst[2];
    const __nv_bfloat16 *ahs[2], *als[2];
#pragma unroll
    for (int i = 0; i < 2; i++) {
        int u = tid + i * THREADS;
        int r = u >> 2, q = u & 3;
        asz[i]  = (row0 + r < Nrows) ? 16 : 0;
        adst[i] = (uint32_t)(r * ASTB + q * 16);
        ahs[i]  = Ah + (size_t)(row0 + r) * K + q * 8;
        als[i]  = Al + (size_t)(row0 + r) * K + q * 8;
    }
    // B staging: 512 16B-units
    constexpr int BU = 512 / THREADS;
    uint32_t bdst[BU];
    const __nv_bfloat16 *bhs[BU], *bls[BU];
#pragma unroll
    for (int i = 0; i < BU; i++) {
        int u = tid + i * THREADS;
        int r = u >> 2, q = u & 3;
        bdst[i] = (uint32_t)(r * ASTB + q * 16);
        bhs[i]  = Wh + (size_t)(col0 + r) * K + q * 8;
        bls[i]  = Wl + (size_t)(col0 + r) * K + q * 8;
    }

    // ldmatrix offsets within a stage
    uint32_t aoff[2], boff[4];
#pragma unroll
    for (int mi = 0; mi < 2; mi++)
        aoff[mi] = (uint32_t)((wm * 32 + mi * 16 + (lane & 15)) * ASTB + (lane >> 4) * 16);
#pragma unroll
    for (int nj2 = 0; nj2 < 4; nj2++)
        boff[nj2] = (uint32_t)((wn * 64 + nj2 * 16 + (lane & 7) + ((lane >> 4) << 3)) * ASTB
                               + ((lane >> 3) & 1) * 16);

    float acc[2][8][4];
#pragma unroll
    for (int mi = 0; mi < 2; mi++)
#pragma unroll
        for (int nj = 0; nj < 8; nj++)
#pragma unroll
            for (int v = 0; v < 4; v++) acc[mi][nj][v] = 0.f;

    const int KT = K / BK;

    auto load_stage = [&](int s, int k0) {
        const uint32_t sb = sbase + (uint32_t)(s * STAGE);
#pragma unroll
        for (int i = 0; i < 2; i++) {
            CP16(sb + O_AH + adst[i], ahs[i] + k0, asz[i]);
            CP16(sb + O_AL + adst[i], als[i] + k0, asz[i]);
        }
#pragma unroll
        for (int i = 0; i < BU; i++) {
            CP16(sb + O_BH + bdst[i], bhs[i] + k0, 16);
            CP16(sb + O_BL + bdst[i], bls[i] + k0, 16);
        }
    };

    load_stage(0, 0);  CP_COMMIT();
    load_stage(1, BK); CP_COMMIT();

    for (int kt = 0; kt < KT; kt++) {
        cp_wait<1>();
        __syncthreads();
        if (kt + 2 < KT) load_stage((kt + 2) % 3, (kt + 2) * BK);
        CP_COMMIT();

        const uint32_t sb = sbase + (uint32_t)((kt % 3) * STAGE);
#pragma unroll
        for (int k16 = 0; k16 < 2; k16++) {
            const uint32_t kb = (uint32_t)(k16 * 32);
            uint32_t ah[2][4], al[2][4], bh[4][4], bl[4][4];
#pragma unroll
            for (int mi = 0; mi < 2; mi++)
                ldmx4(ah[mi][0], ah[mi][1], ah[mi][2], ah[mi][3], sb + O_AH + aoff[mi] + kb);
#pragma unroll
            for (int nj2 = 0; nj2 < 4; nj2++)
                ldmx4(bh[nj2][0], bh[nj2][1], bh[nj2][2], bh[nj2][3], sb + O_BH + boff[nj2] + kb);
            // hi*hi
#pragma unroll
            for (int mi = 0; mi < 2; mi++)
#pragma unroll
                for (int nj = 0; nj < 8; nj++)
                    mma16816(acc[mi][nj], ah[mi],
                             bh[nj >> 1][(nj & 1) * 2], bh[nj >> 1][(nj & 1) * 2 + 1]);
            // hi*lo
#pragma unroll
            for (int nj2 = 0; nj2 < 4; nj2++)
                ldmx4(bl[nj2][0], bl[nj2][1], bl[nj2][2], bl[nj2][3], sb + O_BL + boff[nj2] + kb);
#pragma unroll
            for (int mi = 0; mi < 2; mi++)
#pragma unroll
                for (int nj = 0; nj < 8; nj++)
                    mma16816(acc[mi][nj], ah[mi],
                             bl[nj >> 1][(nj & 1) * 2], bl[nj >> 1][(nj & 1) * 2 + 1]);
            // lo*hi
#pragma unroll
            for (int mi = 0; mi < 2; mi++)
                ldmx4(al[mi][0], al[mi][1], al[mi][2], al[mi][3], sb + O_AL + aoff[mi] + kb);
#pragma unroll
            for (int mi = 0; mi < 2; mi++)
#pragma unroll
                for (int nj = 0; nj < 8; nj++)
                    mma16816(acc[mi][nj], al[mi],
                             bh[nj >> 1][(nj & 1) * 2], bh[nj >> 1][(nj & 1) * 2 + 1]);
        }
    }

    // ---- epilogue ----
    const int g  = lane >> 2;
    const int tg = lane & 3;
#pragma unroll
    for (int mi = 0; mi < 2; mi++) {
#pragma unroll
        for (int half = 0; half < 2; half++) {
            const int r = row0 + wm * 32 + mi * 16 + g + half * 8;
            if (r >= Nrows) continue;
#pragma unroll
            for (int nj = 0; nj < 8; nj++) {
                const int c = col0 + wn * 64 + nj * 8 + tg * 2;
                float v0 = acc[mi][nj][half * 2 + 0] + bias[c];
                float v1 = acc[mi][nj][half * 2 + 1] + bias[c + 1];
                if (EPI == 1) {
                    v0 = 0.5f * v0 * (1.0f + erff(v0 * 0.7071067811865475f));
                    v1 = 0.5f * v1 * (1.0f + erff(v1 * 0.7071067811865475f));
                    __nv_bfloat16 h0, l0, h1, l1;
                    split1(v0, h0, l0); split1(v1, h1, l1);
                    *reinterpret_cast<uint32_t*>(Ch + (size_t)r * M + c) = pack_bf16(h0, h1);
                    *reinterpret_cast<uint32_t*>(Cl + (size_t)r * M + c) = pack_bf16(l0, l1);
                } else {
                    if (EPI == 2) {
                        v0 += res[(size_t)r * M + c];
                        v1 += res[(size_t)r * M + c + 1];
                    }
                    C[(size_t)r * M + c]     = v0;
                    C[(size_t)r * M + c + 1] = v1;
                }
            }
        }
    }
}

// ---------------- LayerNorm -> bf16 hi/lo ----------------
__global__ void __launch_bounds__(256)
ln_kernel(const float* __restrict__ x, const float* __restrict__ s,
          const float* __restrict__ b, __nv_bfloat16* __restrict__ yh,
          __nv_bfloat16* __restrict__ yl)
{
    const int row = blockIdx.x;
    const int tid = threadIdx.x;
    const float* xr = x + (size_t)row * DIM;

    float v0 = xr[tid];
    float v1 = xr[tid + 256];
    float v2 = xr[tid + 512];

    __shared__ float ssum[256], ssq[256];
    ssum[tid] = v0 + v1 + v2;
    ssq[tid]  = v0 * v0 + v1 * v1 + v2 * v2;
    __syncthreads();
    for (int st = 128; st > 0; st >>= 1) {
        if (tid < st) { ssum[tid] += ssum[tid + st]; ssq[tid] += ssq[tid + st]; }
        __syncthreads();
    }
    const float mean = ssum[0] * (1.0f / DIM);
    const float var  = ssq[0] * (1.0f / DIM) - mean * mean;
    const float inv  = rsqrtf(var + 1e-5f);

    __nv_bfloat16 h, l;
    size_t o = (size_t)row * DIM;
    float y0 = (v0 - mean) * inv * s[tid]       + b[tid];
    float y1 = (v1 - mean) * inv * s[tid + 256] + b[tid + 256];
    float y2 = (v2 - mean) * inv * s[tid + 512] + b[tid + 512];
    split1(y0, h, l); yh[o + tid]       = h; yl[o + tid]       = l;
    split1(y1, h, l); yh[o + tid + 256] = h; yl[o + tid + 256] = l;
    split1(y2, h, l); yh[o + tid + 512] = h; yl[o + tid + 512] = l;
}

// ---------------- Attention -> bf16 hi/lo ----------------
__global__ void __launch_bounds__(128)
attn_kernel(const float* __restrict__ qkv, const int* __restrict__ routes,
            __nv_bfloat16* __restrict__ outh, __nv_bfloat16* __restrict__ outl)
{
    __shared__ float sc[4][200];
    __shared__ int   sidx[4][200];
    __shared__ float qs[4][64];

    const int bh   = blockIdx.x;
    const int b    = bh / NHEAD;
    const int h    = bh % NHEAD;
    const int warp = threadIdx.x >> 5;
    const int lane = threadIdx.x & 31;
    const int s    = blockIdx.y * 4 + warp;
    if (s >= SEQ) return;

    const float* base = qkv + (size_t)b * SEQ * (3 * DIM);
    const float* qp = base + (size_t)s * (3 * DIM) + h * HDIM;
    qs[warp][lane]      = qp[lane];
    qs[warp][lane + 32] = qp[lane + 32];
    __syncwarp();

    const int nk = (s == 0) ? SEQ : TOPK;

    for (int j = lane; j < nk; j += 32) {
        int kidx = (s == 0) ? j : (routes[(s - 1) * TOPK + j] + 1);
        const float* kp = base + (size_t)kidx * (3 * DIM) + DIM + h * HDIM;
        float acc = 0.f;
#pragma unroll
        for (int d = 0; d < HDIM; d++) acc = fmaf(qs[warp][d], kp[d], acc);
        sc[warp][j]   = acc * ATT_SCALE;
        sidx[warp][j] = kidx;
    }
    __syncwarp();

    float m = -1e30f;
    for (int j = lane; j < nk; j += 32) m = fmaxf(m, sc[warp][j]);
#pragma unroll
    for (int o = 16; o; o >>= 1) m = fmaxf(m, __shfl_xor_sync(0xffffffffu, m, o));

    float sum = 0.f;
    for (int j = lane; j < nk; j += 32) {
        float e = expf(sc[warp][j] - m);
        sc[warp][j] = e;
        sum += e;
    }
#pragma unroll
    for (int o = 16; o; o >>= 1) sum += __shfl_xor_sync(0xffffffffu, sum, o);
    __syncwarp();
    const float inv = 1.f / sum;

    float o0 = 0.f, o1 = 0.f;
    for (int j = 0; j < nk; j++) {
        float p = sc[warp][j];
        const float* vp = base + (size_t)sidx[warp][j] * (3 * DIM) + 2 * DIM + h * HDIM;
        o0 = fmaf(p, vp[2 * lane],     o0);
        o1 = fmaf(p, vp[2 * lane + 1], o1);
    }
    size_t ob = ((size_t)(b * SEQ + s)) * DIM + h * HDIM;
    __nv_bfloat16 h0, l0, h1, l1;
    split1(o0 * inv, h0, l0);
    split1(o1 * inv, h1, l1);
    *reinterpret_cast<uint32_t*>(outh + ob + 2 * lane) = pack_bf16(h0, h1);
    *reinterpret_cast<uint32_t*>(outl + ob + 2 * lane) = pack_bf16(l0, l1);
}

// ---------------- Patchify -> bf16 hi/lo ----------------
__global__ void patchify_kernel(const float* __restrict__ x,
                                __nv_bfloat16* __restrict__ xph, __nv_bfloat16* __restrict__ xpl)
{
    int idx = blockIdx.x * blockDim.x + threadIdx.x;
    const int total = NROWS_P * DIM;
    if (idx >= total) return;
    int e  = idx % DIM;
    int bp = idx / DIM;
    int p  = bp % NPATCH;
    int b  = bp / NPATCH;
    int c  = e / (PATCH * PATCH);
    int r  = e % (PATCH * PATCH);
    int py = r / PATCH, px = r % PATCH;
    int gy = p / GRID,  gx = p % GRID;
    float v = x[(((size_t)b * CHN + c) * IMG + gy * PATCH + py) * IMG + gx * PATCH + px];
    __nv_bfloat16 h, l;
    split1(v, h, l);
    xph[idx] = h;
    xpl[idx] = l;
}

// ---------------- Assemble ----------------
__global__ void assemble_kernel(const float* __restrict__ tok, const float* __restrict__ cls,
                                const float* __restrict__ pos, float* __restrict__ hout)
{
    int idx = blockIdx.x * blockDim.x + threadIdx.x;
    const int total = BATCH * SEQ * DIM;
    if (idx >= total) return;
    int d  = idx % DIM;
    int bs = idx / DIM;
    int s  = bs % SEQ;
    int b  = bs / SEQ;
    float v = (s == 0) ? cls[d] : tok[((size_t)b * NPATCH + (s - 1)) * DIM + d];
    hout[idx] = v + pos[(size_t)s * DIM + d];
}

// ---------------- host launcher ----------------
extern "C" void kernel_launch(void* const* d_in, const int* in_sizes, int n_in,
                              void* d_out, int out_size)
{
    const float* x        = (const float*)d_in[0];
    const float* patch_w  = (const float*)d_in[1];
    const float* patch_b  = (const float*)d_in[2];
    const float* cls_tok  = (const float*)d_in[3];
    const float* pos_emb  = (const float*)d_in[4];
    const float* qkv_w    = (const float*)d_in[5];
    const float* qkv_b    = (const float*)d_in[6];
    const float* proj_w   = (const float*)d_in[7];
    const float* proj_b   = (const float*)d_in[8];
    const float* ln1_s    = (const float*)d_in[9];
    const float* ln1_b    = (const float*)d_in[10];
    const float* ln2_s    = (const float*)d_in[11];
    const float* ln2_b    = (const float*)d_in[12];
    const float* fc1_w    = (const float*)d_in[13];
    const float* fc1_b    = (const float*)d_in[14];
    const float* fc2_w    = (const float*)d_in[15];
    const float* fc2_b    = (const float*)d_in[16];
    const int*   routes   = (const int*)d_in[17];

    float *hbuf, *qkv;
    __nv_bfloat16 *xnh, *xnl, *atth, *attl, *mlph, *mlpl, *wh, *wl;
    cudaGetSymbolAddress((void**)&hbuf, g_h);
    cudaGetSymbolAddress((void**)&qkv,  g_qkv);
    cudaGetSymbolAddress((void**)&xnh,  g_xnh);
    cudaGetSymbolAddress((void**)&xnl,  g_xnl);
    cudaGetSymbolAddress((void**)&atth, g_atth);
    cudaGetSymbolAddress((void**)&attl, g_attl);
    cudaGetSymbolAddress((void**)&mlph, g_mlph);
    cudaGetSymbolAddress((void**)&mlpl, g_mlpl);
    cudaGetSymbolAddress((void**)&wh,   g_wh);
    cudaGetSymbolAddress((void**)&wl,   g_wl);

    // smem: 3 stages; BM=128 -> 3*40960 = 122880, BM=64 -> 3*30720 = 92160
    const int SMEM128 = 3 * (2 * 128 * 80 + 2 * 128 * 80);
    const int SMEM64  = 3 * (2 * 64 * 80 + 2 * 128 * 80);
    cudaFuncSetAttribute(hgemm<128, 0>, cudaFuncAttributeMaxDynamicSharedMemorySize, SMEM128);
    cudaFuncSetAttribute(hgemm<64, 0>,  cudaFuncAttributeMaxDynamicSharedMemorySize, SMEM64);
    cudaFuncSetAttribute(hgemm<64, 1>,  cudaFuncAttributeMaxDynamicSharedMemorySize, SMEM64);
    cudaFuncSetAttribute(hgemm<64, 2>,  cudaFuncAttributeMaxDynamicSharedMemorySize, SMEM64);

    // ---- one-time weight split ----
    {
        struct { const float* src; int off; int n; } cv[5] = {
            {patch_w, OFF_PATCH, NW_PATCH},
            {qkv_w,   OFF_QKV,   NW_QKV},
            {proj_w,  OFF_PROJ,  NW_PROJ},
            {fc1_w,   OFF_FC1,   NW_FC1},
            {fc2_w,   OFF_FC2,   NW_FC2},
        };
        for (int i = 0; i < 5; i++) {
            int n4 = cv[i].n / 4;
            cvt_weights<<<(n4 + 255) / 256, 256>>>(cv[i].src, wh + cv[i].off, wl + cv[i].off, n4);
        }
    }

    const int rt128 = (NROWS + 127) / 128;   // 13
    const int rt64  = (NROWS + 63) / 64;     // 25
    const int rt64p = (NROWS_P + 63) / 64;   // 25

    // patch embed
    {
        int tot = NROWS_P * DIM;
        patchify_kernel<<<(tot + 255) / 256, 256>>>(x, mlph, mlpl);
        hgemm<64, 0><<<dim3(DIM / 128, rt64p), 128, SMEM64>>>(
            mlph, mlpl, wh + OFF_PATCH, wl + OFF_PATCH, patch_b, nullptr,
            qkv, nullptr, nullptr, NROWS_P, DIM, DIM);
        int tot2 = BATCH * SEQ * DIM;
        assemble_kernel<<<(tot2 + 255) / 256, 256>>>(qkv, cls_tok, pos_emb, hbuf);
    }

    for (int l = 0; l < NLAYER; l++) {
        const size_t oq  = OFF_QKV  + (size_t)l * 3 * DIM * DIM;
        const size_t op  = OFF_PROJ + (size_t)l * DIM * DIM;
        const size_t of1 = OFF_FC1  + (size_t)l * MLPDIM * DIM;
        const size_t of2 = OFF_FC2  + (size_t)l * DIM * MLPDIM;
        const float* qb  = qkv_b  + (size_t)l * 3 * DIM;
        const float* pb  = proj_b + (size_t)l * DIM;
        const float* f1b = fc1_b  + (size_t)l * MLPDIM;
        const float* f2b = fc2_b  + (size_t)l * DIM;

        ln_kernel<<<NROWS, 256>>>(hbuf, ln1_s + (size_t)l * DIM, ln1_b + (size_t)l * DIM,
                                  xnh, xnl);
        hgemm<128, 0><<<dim3(3 * DIM / 128, rt128), 256, SMEM128>>>(
            xnh, xnl, wh + oq, wl + oq, qb, nullptr,
            qkv, nullptr, nullptr, NROWS, DIM, 3 * DIM);
        attn_kernel<<<dim3(BATCH * NHEAD, (SEQ + 3) / 4), 128>>>(qkv, routes, atth, attl);
        hgemm<64, 2><<<dim3(DIM / 128, rt64), 128, SMEM64>>>(
            atth, attl, wh + op, wl + op, pb, hbuf,
            hbuf, nullptr, nullptr, NROWS, DIM, DIM);
        ln_kernel<<<NROWS, 256>>>(hbuf, ln2_s + (size_t)l * DIM, ln2_b + (size_t)l * DIM,
                                  xnh, xnl);
        hgemm<64, 1><<<dim3(MLPDIM / 128, rt64), 128, SMEM64>>>(
            xnh, xnl, wh + of1, wl + of1, f1b, nullptr,
            nullptr, mlph, mlpl, NROWS, DIM, MLPDIM);
        float* outp = (l == NLAYER - 1) ? (float*)d_out : hbuf;
        hgemm<64, 2><<<dim3(DIM / 128, rt64), 128, SMEM64>>>(
            mlph, mlpl, wh + of2, wl + of2, f2b, hbuf,
            outp, nullptr, nullptr, NROWS, MLPDIM, DIM);
    }
}